// round 11
// baseline (speedup 1.0000x reference)
#include <cuda_runtime.h>
#include <cuda_fp16.h>
#include <cuda_bf16.h>
#include <cstdint>

// Problem constants
#define TT 256
#define BB 1024
#define OBS 128
#define LS 128
#define HH 128
#define NA 18
#define MROWS (TT*BB)          // 262144

// ---------------------------------------------------------------------------
// Scratch (device globals; no cudaMalloc allowed)
// ---------------------------------------------------------------------------
__device__ float g_h1[(size_t)MROWS * 128];   // encoder layer-1 out
__device__ float g_h2[(size_t)MROWS * 32];    // encoder layer-2 out
__device__ float g_h3[(size_t)MROWS * 128];   // encoder layer-3 out
__device__ float g_Z [(size_t)MROWS * 512];   // precomputed input gates + biases

// ---------------------------------------------------------------------------
// f32x2 packed-FMA helpers (exact fp32 math, throughput-neutral but fewer inst)
// ---------------------------------------------------------------------------
__device__ __forceinline__ void ffma2(uint64_t& acc, uint64_t a, uint64_t b) {
    asm("fma.rn.f32x2 %0, %1, %2, %0;" : "+l"(acc) : "l"(a), "l"(b));
}
__device__ __forceinline__ uint64_t pack2(float x, float y) {
    uint64_t r;
    asm("mov.b64 %0, {%1, %2};" : "=l"(r) : "f"(x), "f"(y));
    return r;
}
__device__ __forceinline__ void unpack2(uint64_t v, float& lo, float& hi) {
    asm("mov.b64 {%0, %1}, %2;" : "=f"(lo), "=f"(hi) : "l"(v));
}

// ---------------------------------------------------------------------------
// Fast nonlinearities (MUFU; fma pipe stays free)
// ---------------------------------------------------------------------------
__device__ __forceinline__ float sigm_fast(float x) {
    x = fminf(fmaxf(x, -30.f), 30.f);
    return __fdividef(1.f, 1.f + __expf(-x));
}
__device__ __forceinline__ float tanh_fast(float x) {
    x = fminf(fmaxf(x, -15.f), 15.f);
    float e = __expf(-2.f * x);
    return __fdividef(1.f - e, 1.f + e);
}

// ---------------------------------------------------------------------------
// Tiled SIMT GEMM (UNCHANGED from R10 — at SIMT roofline: fma~90%, L1~86%)
// ---------------------------------------------------------------------------
template<int KT, int NT, bool RELU>
__global__ void __launch_bounds__(256, 2) gemm_kernel(
    const float* __restrict__ A, const float* __restrict__ W,
    const float* __restrict__ bias1, const float* __restrict__ bias2,
    float* __restrict__ C, int N)
{
    constexpr int AP  = 68;
    constexpr int BP  = NT + 4;
    constexpr int KQ  = KT / 4;
    constexpr int CPT = NT / 32;

    extern __shared__ float smg[];
    float* As = smg;
    float* Bs = smg + KT * AP;

    const int  tid  = threadIdx.x;
    const long row0 = (long)blockIdx.x * 64;
    const int  c0   = blockIdx.y * NT;

    for (int idx = tid; idx < KQ * 64; idx += 256) {
        int kq = idx / 64, r = idx % 64;
        float4 v = *reinterpret_cast<const float4*>(A + (row0 + r) * KT + kq * 4);
        As[(kq*4+0)*AP + r] = v.x;
        As[(kq*4+1)*AP + r] = v.y;
        As[(kq*4+2)*AP + r] = v.z;
        As[(kq*4+3)*AP + r] = v.w;
    }
    for (int idx = tid; idx < KQ * NT; idx += 256) {
        int kq = idx / NT, jj = idx % NT;
        float4 v = *reinterpret_cast<const float4*>(W + (long)(c0 + jj) * KT + kq * 4);
        Bs[(kq*4+0)*BP + jj] = v.x;
        Bs[(kq*4+1)*BP + jj] = v.y;
        Bs[(kq*4+2)*BP + jj] = v.z;
        Bs[(kq*4+3)*BP + jj] = v.w;
    }
    __syncthreads();

    const int tx = tid & 31, ty = tid >> 5;
    uint64_t acc2[4][CPT];
    #pragma unroll
    for (int i2 = 0; i2 < 4; ++i2)
        #pragma unroll
        for (int c = 0; c < CPT; ++c) acc2[i2][c] = 0ull;

    #pragma unroll 8
    for (int k = 0; k < KT; ++k) {
        ulonglong2 av0 = *reinterpret_cast<const ulonglong2*>(&As[k * AP + ty * 8]);
        ulonglong2 av1 = *reinterpret_cast<const ulonglong2*>(&As[k * AP + ty * 8 + 4]);
        uint64_t ap[4] = {av0.x, av0.y, av1.x, av1.y};
        float bb[CPT];
        if constexpr (CPT == 4) {
            float4 bv = *reinterpret_cast<const float4*>(&Bs[k * BP + tx * 4]);
            bb[0] = bv.x; bb[1] = bv.y; bb[2] = bv.z; bb[3] = bv.w;
        } else {
            bb[0] = Bs[k * BP + tx];
        }
        #pragma unroll
        for (int c = 0; c < CPT; ++c) {
            uint64_t bd = pack2(bb[c], bb[c]);
            #pragma unroll
            for (int i2 = 0; i2 < 4; ++i2)
                ffma2(acc2[i2][c], ap[i2], bd);
        }
    }

    float acc[8][CPT];
    #pragma unroll
    for (int i2 = 0; i2 < 4; ++i2)
        #pragma unroll
        for (int c = 0; c < CPT; ++c)
            unpack2(acc2[i2][c], acc[2*i2][c], acc[2*i2+1][c]);

    if constexpr (CPT == 4) {
        float bsum[4];
        #pragma unroll
        for (int c = 0; c < 4; ++c) {
            int col = c0 + tx * 4 + c;
            bsum[c] = bias1[col] + (bias2 ? bias2[col] : 0.f);
        }
        #pragma unroll
        for (int i = 0; i < 8; ++i) {
            long row = row0 + ty * 8 + i;
            float4 o;
            o.x = acc[i][0] + bsum[0];
            o.y = acc[i][1] + bsum[1];
            o.z = acc[i][2] + bsum[2];
            o.w = acc[i][3] + bsum[3];
            if (RELU) {
                o.x = fmaxf(o.x, 0.f); o.y = fmaxf(o.y, 0.f);
                o.z = fmaxf(o.z, 0.f); o.w = fmaxf(o.w, 0.f);
            }
            *reinterpret_cast<float4*>(C + row * N + c0 + tx * 4) = o;
        }
    } else {
        int col = c0 + tx;
        float bsum = bias1[col] + (bias2 ? bias2[col] : 0.f);
        #pragma unroll
        for (int i = 0; i < 8; ++i) {
            long row = row0 + ty * 8 + i;
            float v = acc[i][0] + bsum;
            if (RELU) v = fmaxf(v, 0.f);
            C[row * N + col] = v;
        }
    }
}

// ---------------------------------------------------------------------------
// Persistent LSTM recurrence + heads — 1024 threads (32 warps) per CTA.
// 128 CTAs x 8 lanes; thread = (gate j = tid&511, lane-half hf = tid>>9).
// Per thread per step: 4 dot-products of 128 (2 f32x2 accumulators).
// Whh fp16 in smem (proven 1e-4); h fp32 pair-interleaved (broadcast loads).
// ---------------------------------------------------------------------------
#define OFF_WSH   0                         // 512*128 half   = 131072
#define OFF_HBUF  131072                    // 8*128 f32      =   4096
#define OFF_CBUF  135168                    //                =   4096
#define OFF_HP    139264                    // 4*128 float2   =   4096
#define OFF_GBUF  143360                    // 512*9 f32      =  18432
#define OFF_WAC   161792                    // 19*132 f32     =  10048 (pad)
#define OFF_BAC   171840                    // 19 f32         =     80 (pad)
#define OFF_MS    171920                    // 2*8 f32        =     64
#define SMEM_LSTM 171984

__global__ void __launch_bounds__(1024, 1) lstm_kernel(
    const float* __restrict__ Z,    const float* __restrict__ done,
    const float* __restrict__ h0,   const float* __restrict__ c0,
    const float* __restrict__ Whh,
    const float* __restrict__ Wa,   const float* __restrict__ ba,
    const float* __restrict__ Wc,   const float* __restrict__ bc,
    float* __restrict__ out)
{
    extern __shared__ char smraw[];
    __half*  wsh  = reinterpret_cast<__half*>(smraw + OFF_WSH);
    float*   hbuf = reinterpret_cast<float*>(smraw + OFF_HBUF);
    float*   cbuf = reinterpret_cast<float*>(smraw + OFF_CBUF);
    float2*  hp   = reinterpret_cast<float2*>(smraw + OFF_HP);
    float*   gbuf = reinterpret_cast<float*>(smraw + OFF_GBUF);
    float*   WaCs = reinterpret_cast<float*>(smraw + OFF_WAC);
    float*   bac  = reinterpret_cast<float*>(smraw + OFF_BAC);
    float*   ms   = reinterpret_cast<float*>(smraw + OFF_MS);

    const int tid = threadIdx.x;
    const int gb0 = blockIdx.x * 8;        // 128 CTAs x 8 lanes = 1024

    // --- Whh -> fp16 smem, layout: ((k>>2)<<11) + (j<<2) + (k&3)
    for (int idx = tid; idx < 512 * 128; idx += 1024) {
        int jj = idx >> 7, k = idx & 127;
        wsh[((k >> 2) << 11) + (jj << 2) + (k & 3)] = __float2half(Whh[idx]);
    }
    // --- h0/c0 per-lane fp32
    if (tid < 8 * 128) {
        int b = tid >> 7, u = tid & 127;
        hbuf[tid] = h0[(gb0 + b) * HH + u];
        cbuf[tid] = c0[(gb0 + b) * HH + u];
    }
    // --- h0 pair-interleaved for the f32x2 matvec
    if (tid < 4 * 128) {
        int p = tid >> 7, k = tid & 127;
        hp[p * 128 + k] = make_float2(h0[(gb0 + 2*p) * HH + k],
                                      h0[(gb0 + 2*p + 1) * HH + k]);
    }
    // --- head weights (Wa rows 0..17, Wc row 18), ld=132
    for (int idx = tid; idx < 19 * 128; idx += 1024) {
        int a = idx >> 7, k = idx & 127;
        WaCs[a * 132 + k] = (a < 18) ? Wa[a * 128 + k] : Wc[k];
    }
    if (tid < 19) bac[tid] = (tid < 18) ? ba[tid] : bc[0];
    if (tid < 8)  ms[tid]  = 1.f - done[gb0 + tid];   // slot 0 = mask for t=0
    __syncthreads();

    const int j    = tid & 511;    // gate index 0..511
    const int type = j >> 7;       // 0=i,1=f,2=g,3=o (warp-uniform)
    const int hf   = tid >> 9;     // lane half: 0 -> lanes 0..3, 1 -> lanes 4..7
    const int p0   = hf << 1;      // first pair index (warp-uniform)

    for (int t = 0; t < TT; ++t) {
        const int slot  = (t & 1) * 8;
        const int nslot = ((t + 1) & 1) * 8;

        // ---- Phase A: gates = sigma( m_t * (Whh @ h) + Z ) ----
        float zr[4];
        const long zbase = ((long)t * BB + gb0 + (hf << 2)) * 512 + j;
        #pragma unroll
        for (int b = 0; b < 4; ++b)
            zr[b] = Z[zbase + (long)b * 512];
        float dn = 0.f;
        if (tid < 8)
            dn = (t < TT - 1) ? done[(t + 1) * BB + gb0 + tid] : 0.f;
        float mk[4];
        #pragma unroll
        for (int b = 0; b < 4; ++b) mk[b] = ms[slot + (hf << 2) + b];

        uint64_t acc2[2] = {0ull, 0ull};
        #pragma unroll 4
        for (int k4 = 0; k4 < 32; ++k4) {
            uint2 wr = *reinterpret_cast<const uint2*>(wsh + (k4 << 11) + (j << 2));
            float2 w01 = __half22float2(*reinterpret_cast<const __half2*>(&wr.x));
            float2 w23 = __half22float2(*reinterpret_cast<const __half2*>(&wr.y));
            uint64_t wd0 = pack2(w01.x, w01.x);
            uint64_t wd1 = pack2(w01.y, w01.y);
            uint64_t wd2 = pack2(w23.x, w23.x);
            uint64_t wd3 = pack2(w23.y, w23.y);
            // broadcast loads (warp-uniform addresses)
            ulonglong2 ha0 = *reinterpret_cast<const ulonglong2*>(&hp[(p0 << 7) + (k4 << 2)]);
            ulonglong2 hb0 = *reinterpret_cast<const ulonglong2*>(&hp[(p0 << 7) + (k4 << 2) + 2]);
            ulonglong2 ha1 = *reinterpret_cast<const ulonglong2*>(&hp[((p0 + 1) << 7) + (k4 << 2)]);
            ulonglong2 hb1 = *reinterpret_cast<const ulonglong2*>(&hp[((p0 + 1) << 7) + (k4 << 2) + 2]);
            ffma2(acc2[0], wd0, ha0.x);  ffma2(acc2[1], wd0, ha1.x);
            ffma2(acc2[0], wd1, ha0.y);  ffma2(acc2[1], wd1, ha1.y);
            ffma2(acc2[0], wd2, hb0.x);  ffma2(acc2[1], wd2, hb1.x);
            ffma2(acc2[0], wd3, hb0.y);  ffma2(acc2[1], wd3, hb1.y);
        }
        float av[4];
        unpack2(acc2[0], av[0], av[1]);
        unpack2(acc2[1], av[2], av[3]);
        #pragma unroll
        for (int b = 0; b < 4; ++b) {
            float v = fmaf(av[b], mk[b], zr[b]);      // mask folded: m*(W@h)+Z
            float gv = (type == 2) ? tanh_fast(v) : sigm_fast(v);
            gbuf[j * 9 + (hf << 2) + b] = gv;
        }
        if (tid < 8) ms[nslot + tid] = 1.f - dn;      // mask for step t+1
        __syncthreads();

        // ---- Phase B1: c,h update (c masked here); 1024 threads, one pass ----
        {
            int b = tid >> 7, u = tid & 127;
            float m = ms[slot + b];
            int gbase = u * 9 + b;
            float iv = gbuf[gbase];
            float fv = gbuf[gbase + 128 * 9];
            float gg = gbuf[gbase + 256 * 9];
            float ov = gbuf[gbase + 384 * 9];
            float cv = fmaf(fv, cbuf[tid] * m, iv * gg);
            float hv = ov * tanh_fast(cv);
            cbuf[tid] = cv;
            hbuf[tid] = hv;
            reinterpret_cast<float*>(hp)[(((b >> 1) << 7) + u) * 2 + (b & 1)] = hv;
        }
        __syncthreads();

        // ---- Phase B2: heads (18 logits + 1 value) ----
        if (tid < 8 * 19) {
            int b = tid / 19, a = tid - b * 19;
            float s0 = 0.f, s1 = 0.f;
            #pragma unroll 4
            for (int k8 = 0; k8 < 16; ++k8) {
                float4 w0 = *reinterpret_cast<const float4*>(&WaCs[a * 132 + k8 * 8]);
                float4 w1 = *reinterpret_cast<const float4*>(&WaCs[a * 132 + k8 * 8 + 4]);
                float4 hv0 = *reinterpret_cast<const float4*>(&hbuf[b * 128 + k8 * 8]);
                float4 hv1 = *reinterpret_cast<const float4*>(&hbuf[b * 128 + k8 * 8 + 4]);
                s0 = fmaf(w0.x, hv0.x, s0); s0 = fmaf(w0.y, hv0.y, s0);
                s0 = fmaf(w0.z, hv0.z, s0); s0 = fmaf(w0.w, hv0.w, s0);
                s1 = fmaf(w1.x, hv1.x, s1); s1 = fmaf(w1.y, hv1.y, s1);
                s1 = fmaf(w1.z, hv1.z, s1); s1 = fmaf(w1.w, hv1.w, s1);
            }
            out[((long)t * BB + gb0 + b) * 19 + a] = s0 + s1 + bac[a];
        }
        __syncthreads();
    }
}

// ---------------------------------------------------------------------------
// Host launcher
// ---------------------------------------------------------------------------
extern "C" void kernel_launch(void* const* d_in, const int* in_sizes, int n_in,
                              void* d_out, int out_size)
{
    const float* x    = (const float*)d_in[0];
    const float* done = (const float*)d_in[1];
    const float* h0   = (const float*)d_in[2];
    const float* c0   = (const float*)d_in[3];
    const float* W1   = (const float*)d_in[4];
    const float* b1   = (const float*)d_in[5];
    const float* W2   = (const float*)d_in[6];
    const float* b2   = (const float*)d_in[7];
    const float* W3   = (const float*)d_in[8];
    const float* b3   = (const float*)d_in[9];
    const float* Wih  = (const float*)d_in[10];
    const float* Whh  = (const float*)d_in[11];
    const float* bih  = (const float*)d_in[12];
    const float* bhh  = (const float*)d_in[13];
    const float* Wa   = (const float*)d_in[14];
    const float* ba   = (const float*)d_in[15];
    const float* Wc   = (const float*)d_in[16];
    const float* bc   = (const float*)d_in[17];
    float* out = (float*)d_out;

    float *h1p, *h2p, *h3p, *Zp;
    cudaGetSymbolAddress((void**)&h1p, g_h1);
    cudaGetSymbolAddress((void**)&h2p, g_h2);
    cudaGetSymbolAddress((void**)&h3p, g_h3);
    cudaGetSymbolAddress((void**)&Zp,  g_Z);

    const int S_128_128 = (128 * 68 + 128 * 132) * 4;  // 102400
    const int S_128_32  = (128 * 68 + 128 * 36)  * 4;  //  53248
    const int S_32_128  = (32  * 68 + 32  * 132) * 4;  //  25600

    cudaFuncSetAttribute(gemm_kernel<128, 128, true>,
                         cudaFuncAttributeMaxDynamicSharedMemorySize, S_128_128);
    cudaFuncSetAttribute(gemm_kernel<128, 128, false>,
                         cudaFuncAttributeMaxDynamicSharedMemorySize, S_128_128);
    cudaFuncSetAttribute(gemm_kernel<128, 32, true>,
                         cudaFuncAttributeMaxDynamicSharedMemorySize, S_128_32);
    cudaFuncSetAttribute(gemm_kernel<32, 128, true>,
                         cudaFuncAttributeMaxDynamicSharedMemorySize, S_32_128);
    cudaFuncSetAttribute(lstm_kernel,
                         cudaFuncAttributeMaxDynamicSharedMemorySize, SMEM_LSTM);

    const int NT_ROW = MROWS / 64;  // 4096 row tiles

    // Encoder
    gemm_kernel<128, 128, true><<<dim3(NT_ROW, 1), 256, S_128_128>>>(
        x,   W1, b1, nullptr, h1p, 128);
    gemm_kernel<128, 32, true><<<dim3(NT_ROW, 1), 256, S_128_32>>>(
        h1p, W2, b2, nullptr, h2p, 32);
    gemm_kernel<32, 128, true><<<dim3(NT_ROW, 1), 256, S_32_128>>>(
        h2p, W3, b3, nullptr, h3p, 128);
    // Input projection: Z = hid @ Wih^T + bih + bhh   (N = 512, 4 col tiles)
    gemm_kernel<128, 128, false><<<dim3(NT_ROW, 4), 256, S_128_128>>>(
        h3p, Wih, bih, bhh, Zp, 512);

    // Recurrence + heads (1024 threads, 32 warps per CTA)
    lstm_kernel<<<128, 1024, SMEM_LSTM>>>(
        Zp, done, h0, c0, Whh, Wa, ba, Wc, bc, out);
}

// round 12
// speedup vs baseline: 1.0383x; 1.0383x over previous
#include <cuda_runtime.h>
#include <cuda_fp16.h>
#include <cuda_bf16.h>
#include <cstdint>

// Problem constants
#define TT 256
#define BB 1024
#define OBS 128
#define LS 128
#define HH 128
#define NA 18
#define MROWS (TT*BB)          // 262144

// ---------------------------------------------------------------------------
// Scratch (device globals; no cudaMalloc allowed)
// ---------------------------------------------------------------------------
__device__ float g_h1[(size_t)MROWS * 128];   // encoder layer-1 out
__device__ float g_h2[(size_t)MROWS * 32];    // encoder layer-2 out
__device__ float g_h3[(size_t)MROWS * 128];   // encoder layer-3 out
__device__ float g_Z [(size_t)MROWS * 512];   // precomputed input gates + biases

// ---------------------------------------------------------------------------
// f32x2 packed-FMA helpers (exact fp32 math; 2 MACs per issued inst)
// ---------------------------------------------------------------------------
__device__ __forceinline__ void ffma2(uint64_t& acc, uint64_t a, uint64_t b) {
    asm("fma.rn.f32x2 %0, %1, %2, %0;" : "+l"(acc) : "l"(a), "l"(b));
}
__device__ __forceinline__ uint64_t pack2(float x, float y) {
    uint64_t r;
    asm("mov.b64 %0, {%1, %2};" : "=l"(r) : "f"(x), "f"(y));
    return r;
}
__device__ __forceinline__ void unpack2(uint64_t v, float& lo, float& hi) {
    asm("mov.b64 {%0, %1}, %2;" : "=f"(lo), "=f"(hi) : "l"(v));
}

// ---------------------------------------------------------------------------
// Fast nonlinearities (MUFU; fma pipe stays free)
// ---------------------------------------------------------------------------
__device__ __forceinline__ float sigm_fast(float x) {
    x = fminf(fmaxf(x, -30.f), 30.f);
    return __fdividef(1.f, 1.f + __expf(-x));
}
__device__ __forceinline__ float tanh_fast(float x) {
    x = fminf(fmaxf(x, -15.f), 15.f);
    float e = __expf(-2.f * x);
    return __fdividef(1.f - e, 1.f + e);
}

// ---------------------------------------------------------------------------
// NEW: high-intensity GEMM. 512 threads, tile 128 x NT (NT=128 or 256),
// per-thread 8 rows x (NT/32) cols.  A-frag loads are warp-uniform
// broadcasts; LDS bytes/MAC halved vs the old 8x4 kernel (fix for L1=87%).
//   C[M][NT-tile] = act( A[M][K] @ W[N][K]^T + b1 (+b2) )
// ---------------------------------------------------------------------------
template<int KT, int NT, bool RELU>
__global__ void __launch_bounds__(512) gemm_big(
    const float* __restrict__ A, const float* __restrict__ W,
    const float* __restrict__ bias1, const float* __restrict__ bias2,
    float* __restrict__ C, int N)
{
    constexpr int BP  = NT + 4;     // padded B leading dim
    constexpr int KQ  = KT / 4;
    constexpr int CPT = NT / 32;    // cols per thread (8 or 4)

    extern __shared__ float smg[];
    float* As = smg;                // KT * 128  (A transposed: As[k][row])
    float* Bs = smg + KT * 128;     // KT * BP   (Bs[k][col])

    const int  tid  = threadIdx.x;
    const long row0 = (long)blockIdx.x * 128;
    const int  c0   = blockIdx.y * NT;

    // Stage A tile transposed: 128 rows x KT
    for (int idx = tid; idx < KQ * 128; idx += 512) {
        int kq = idx / 128, r = idx % 128;
        float4 v = *reinterpret_cast<const float4*>(A + (row0 + r) * KT + kq * 4);
        As[(kq*4+0)*128 + r] = v.x;
        As[(kq*4+1)*128 + r] = v.y;
        As[(kq*4+2)*128 + r] = v.z;
        As[(kq*4+3)*128 + r] = v.w;
    }
    // Stage B (=W) tile transposed: NT cols x KT
    for (int idx = tid; idx < KQ * NT; idx += 512) {
        int kq = idx / NT, jj = idx % NT;
        float4 v = *reinterpret_cast<const float4*>(W + (long)(c0 + jj) * KT + kq * 4);
        Bs[(kq*4+0)*BP + jj] = v.x;
        Bs[(kq*4+1)*BP + jj] = v.y;
        Bs[(kq*4+2)*BP + jj] = v.z;
        Bs[(kq*4+3)*BP + jj] = v.w;
    }
    __syncthreads();

    const int lane = tid & 31;       // -> col group
    const int ty2  = tid >> 5;       // 0..15 -> row group (warp-uniform)
    const int rbase = ty2 * 8;
    const int cbase = lane * CPT;

    uint64_t acc2[4][CPT];           // [row-pair][col]
    #pragma unroll
    for (int rp = 0; rp < 4; ++rp)
        #pragma unroll
        for (int c = 0; c < CPT; ++c) acc2[rp][c] = 0ull;

    #pragma unroll 4
    for (int k = 0; k < KT; ++k) {
        // A fragment: 8 row-values, warp-uniform broadcast (2x LDS.128)
        ulonglong2 av0 = *reinterpret_cast<const ulonglong2*>(&As[k * 128 + rbase]);
        ulonglong2 av1 = *reinterpret_cast<const ulonglong2*>(&As[k * 128 + rbase + 4]);
        uint64_t ap[4] = {av0.x, av0.y, av1.x, av1.y};
        // B fragment: CPT col-values
        float bb[CPT];
        #pragma unroll
        for (int c4 = 0; c4 < CPT; c4 += 4) {
            float4 bv = *reinterpret_cast<const float4*>(&Bs[k * BP + cbase + c4]);
            bb[c4+0] = bv.x; bb[c4+1] = bv.y; bb[c4+2] = bv.z; bb[c4+3] = bv.w;
        }
        #pragma unroll
        for (int c = 0; c < CPT; ++c) {
            uint64_t bd = pack2(bb[c], bb[c]);
            #pragma unroll
            for (int rp = 0; rp < 4; ++rp)
                ffma2(acc2[rp][c], ap[rp], bd);
        }
    }

    // Unpack row pairs
    float acc[8][CPT];
    #pragma unroll
    for (int rp = 0; rp < 4; ++rp)
        #pragma unroll
        for (int c = 0; c < CPT; ++c)
            unpack2(acc2[rp][c], acc[2*rp][c], acc[2*rp+1][c]);

    // Epilogue
    float bsum[CPT];
    #pragma unroll
    for (int c = 0; c < CPT; ++c) {
        int col = c0 + cbase + c;
        bsum[c] = bias1[col] + (bias2 ? bias2[col] : 0.f);
    }
    #pragma unroll
    for (int i = 0; i < 8; ++i) {
        long row = row0 + rbase + i;
        #pragma unroll
        for (int c4 = 0; c4 < CPT; c4 += 4) {
            float4 o;
            o.x = acc[i][c4+0] + bsum[c4+0];
            o.y = acc[i][c4+1] + bsum[c4+1];
            o.z = acc[i][c4+2] + bsum[c4+2];
            o.w = acc[i][c4+3] + bsum[c4+3];
            if (RELU) {
                o.x = fmaxf(o.x, 0.f); o.y = fmaxf(o.y, 0.f);
                o.z = fmaxf(o.z, 0.f); o.w = fmaxf(o.w, 0.f);
            }
            *reinterpret_cast<float4*>(C + row * N + c0 + cbase + c4) = o;
        }
    }
}

// ---------------------------------------------------------------------------
// OLD proven GEMM (kept for the small layers W2 / W3)
// ---------------------------------------------------------------------------
template<int KT, int NT, bool RELU>
__global__ void __launch_bounds__(256, 2) gemm_kernel(
    const float* __restrict__ A, const float* __restrict__ W,
    const float* __restrict__ bias1, const float* __restrict__ bias2,
    float* __restrict__ C, int N)
{
    constexpr int AP  = 68;
    constexpr int BP  = NT + 4;
    constexpr int KQ  = KT / 4;
    constexpr int CPT = NT / 32;

    extern __shared__ float smg[];
    float* As = smg;
    float* Bs = smg + KT * AP;

    const int  tid  = threadIdx.x;
    const long row0 = (long)blockIdx.x * 64;
    const int  c0   = blockIdx.y * NT;

    for (int idx = tid; idx < KQ * 64; idx += 256) {
        int kq = idx / 64, r = idx % 64;
        float4 v = *reinterpret_cast<const float4*>(A + (row0 + r) * KT + kq * 4);
        As[(kq*4+0)*AP + r] = v.x;
        As[(kq*4+1)*AP + r] = v.y;
        As[(kq*4+2)*AP + r] = v.z;
        As[(kq*4+3)*AP + r] = v.w;
    }
    for (int idx = tid; idx < KQ * NT; idx += 256) {
        int kq = idx / NT, jj = idx % NT;
        float4 v = *reinterpret_cast<const float4*>(W + (long)(c0 + jj) * KT + kq * 4);
        Bs[(kq*4+0)*BP + jj] = v.x;
        Bs[(kq*4+1)*BP + jj] = v.y;
        Bs[(kq*4+2)*BP + jj] = v.z;
        Bs[(kq*4+3)*BP + jj] = v.w;
    }
    __syncthreads();

    const int tx = tid & 31, ty = tid >> 5;
    uint64_t acc2[4][CPT];
    #pragma unroll
    for (int i2 = 0; i2 < 4; ++i2)
        #pragma unroll
        for (int c = 0; c < CPT; ++c) acc2[i2][c] = 0ull;

    #pragma unroll 8
    for (int k = 0; k < KT; ++k) {
        ulonglong2 av0 = *reinterpret_cast<const ulonglong2*>(&As[k * AP + ty * 8]);
        ulonglong2 av1 = *reinterpret_cast<const ulonglong2*>(&As[k * AP + ty * 8 + 4]);
        uint64_t ap[4] = {av0.x, av0.y, av1.x, av1.y};
        float bb[CPT];
        if constexpr (CPT == 4) {
            float4 bv = *reinterpret_cast<const float4*>(&Bs[k * BP + tx * 4]);
            bb[0] = bv.x; bb[1] = bv.y; bb[2] = bv.z; bb[3] = bv.w;
        } else {
            bb[0] = Bs[k * BP + tx];
        }
        #pragma unroll
        for (int c = 0; c < CPT; ++c) {
            uint64_t bd = pack2(bb[c], bb[c]);
            #pragma unroll
            for (int i2 = 0; i2 < 4; ++i2)
                ffma2(acc2[i2][c], ap[i2], bd);
        }
    }

    float acc[8][CPT];
    #pragma unroll
    for (int i2 = 0; i2 < 4; ++i2)
        #pragma unroll
        for (int c = 0; c < CPT; ++c)
            unpack2(acc2[i2][c], acc[2*i2][c], acc[2*i2+1][c]);

    if constexpr (CPT == 4) {
        float bsum[4];
        #pragma unroll
        for (int c = 0; c < 4; ++c) {
            int col = c0 + tx * 4 + c;
            bsum[c] = bias1[col] + (bias2 ? bias2[col] : 0.f);
        }
        #pragma unroll
        for (int i = 0; i < 8; ++i) {
            long row = row0 + ty * 8 + i;
            float4 o;
            o.x = acc[i][0] + bsum[0];
            o.y = acc[i][1] + bsum[1];
            o.z = acc[i][2] + bsum[2];
            o.w = acc[i][3] + bsum[3];
            if (RELU) {
                o.x = fmaxf(o.x, 0.f); o.y = fmaxf(o.y, 0.f);
                o.z = fmaxf(o.z, 0.f); o.w = fmaxf(o.w, 0.f);
            }
            *reinterpret_cast<float4*>(C + row * N + c0 + tx * 4) = o;
        }
    } else {
        int col = c0 + tx;
        float bsum = bias1[col] + (bias2 ? bias2[col] : 0.f);
        #pragma unroll
        for (int i = 0; i < 8; ++i) {
            long row = row0 + ty * 8 + i;
            float v = acc[i][0] + bsum;
            if (RELU) v = fmaxf(v, 0.f);
            C[row * N + col] = v;
        }
    }
}

// ---------------------------------------------------------------------------
// Persistent LSTM recurrence + heads (R10 best variant, byte-identical).
// 128 CTAs x 512 threads; 8 lanes/CTA; Whh fp16 smem; f32x2 matvec.
// ---------------------------------------------------------------------------
#define OFF_WSH   0                         // 512*128 half   = 131072
#define OFF_HBUF  131072                    // 8*128 f32      =   4096
#define OFF_CBUF  135168                    //                =   4096
#define OFF_HP    139264                    // 4*128 float2   =   4096
#define OFF_GBUF  143360                    // 512*9 f32      =  18432
#define OFF_WAC   161792                    // 19*132 f32     =  10048 (pad)
#define OFF_BAC   171840                    // 19 f32         =     80 (pad)
#define OFF_MS    171920                    // 2*8 f32        =     64
#define SMEM_LSTM 171984

__global__ void __launch_bounds__(512, 1) lstm_kernel(
    const float* __restrict__ Z,    const float* __restrict__ done,
    const float* __restrict__ h0,   const float* __restrict__ c0,
    const float* __restrict__ Whh,
    const float* __restrict__ Wa,   const float* __restrict__ ba,
    const float* __restrict__ Wc,   const float* __restrict__ bc,
    float* __restrict__ out)
{
    extern __shared__ char smraw[];
    __half*  wsh  = reinterpret_cast<__half*>(smraw + OFF_WSH);
    float*   hbuf = reinterpret_cast<float*>(smraw + OFF_HBUF);
    float*   cbuf = reinterpret_cast<float*>(smraw + OFF_CBUF);
    float2*  hp   = reinterpret_cast<float2*>(smraw + OFF_HP);
    float*   gbuf = reinterpret_cast<float*>(smraw + OFF_GBUF);
    float*   WaCs = reinterpret_cast<float*>(smraw + OFF_WAC);
    float*   bac  = reinterpret_cast<float*>(smraw + OFF_BAC);
    float*   ms   = reinterpret_cast<float*>(smraw + OFF_MS);

    const int tid = threadIdx.x;
    const int gb0 = blockIdx.x * 8;        // 128 CTAs x 8 lanes = 1024

    for (int idx = tid; idx < 512 * 128; idx += 512) {
        int jj = idx >> 7, k = idx & 127;
        wsh[((k >> 2) << 11) + (jj << 2) + (k & 3)] = __float2half(Whh[idx]);
    }
    for (int idx = tid; idx < 8 * 128; idx += 512) {
        int b = idx >> 7, u = idx & 127;
        hbuf[idx] = h0[(gb0 + b) * HH + u];
        cbuf[idx] = c0[(gb0 + b) * HH + u];
    }
    for (int idx = tid; idx < 4 * 128; idx += 512) {
        int p = idx >> 7, k = idx & 127;
        hp[p * 128 + k] = make_float2(h0[(gb0 + 2*p) * HH + k],
                                      h0[(gb0 + 2*p + 1) * HH + k]);
    }
    for (int idx = tid; idx < 19 * 128; idx += 512) {
        int a = idx >> 7, k = idx & 127;
        WaCs[a * 132 + k] = (a < 18) ? Wa[a * 128 + k] : Wc[k];
    }
    if (tid < 19) bac[tid] = (tid < 18) ? ba[tid] : bc[0];
    if (tid < 8)  ms[tid]  = 1.f - done[gb0 + tid];
    __syncthreads();

    const int j    = tid;
    const int type = j >> 7;

    for (int t = 0; t < TT; ++t) {
        const int slot  = (t & 1) * 8;
        const int nslot = ((t + 1) & 1) * 8;

        float zr[8];
        const long zbase = ((long)t * BB + gb0) * 512 + j;
        #pragma unroll
        for (int b = 0; b < 8; ++b)
            zr[b] = Z[zbase + (long)b * 512];
        float dn = 0.f;
        if (tid < 8)
            dn = (t < TT - 1) ? done[(t + 1) * BB + gb0 + tid] : 0.f;
        float mk[8];
        #pragma unroll
        for (int b = 0; b < 8; ++b) mk[b] = ms[slot + b];

        uint64_t acc2[4] = {0ull, 0ull, 0ull, 0ull};
        #pragma unroll 4
        for (int k4 = 0; k4 < 32; ++k4) {
            uint2 wr = *reinterpret_cast<const uint2*>(wsh + (k4 << 11) + (j << 2));
            float2 w01 = __half22float2(*reinterpret_cast<const __half2*>(&wr.x));
            float2 w23 = __half22float2(*reinterpret_cast<const __half2*>(&wr.y));
            uint64_t wd0 = pack2(w01.x, w01.x);
            uint64_t wd1 = pack2(w01.y, w01.y);
            uint64_t wd2 = pack2(w23.x, w23.x);
            uint64_t wd3 = pack2(w23.y, w23.y);
            ulonglong2 ha[4], hb[4];
            #pragma unroll
            for (int p = 0; p < 4; ++p) {
                ha[p] = *reinterpret_cast<const ulonglong2*>(&hp[(p << 7) + (k4 << 2)]);
                hb[p] = *reinterpret_cast<const ulonglong2*>(&hp[(p << 7) + (k4 << 2) + 2]);
            }
            #pragma unroll
            for (int p = 0; p < 4; ++p) ffma2(acc2[p], wd0, ha[p].x);
            #pragma unroll
            for (int p = 0; p < 4; ++p) ffma2(acc2[p], wd1, ha[p].y);
            #pragma unroll
            for (int p = 0; p < 4; ++p) ffma2(acc2[p], wd2, hb[p].x);
            #pragma unroll
            for (int p = 0; p < 4; ++p) ffma2(acc2[p], wd3, hb[p].y);
        }
        float av[8];
        #pragma unroll
        for (int p = 0; p < 4; ++p) unpack2(acc2[p], av[2*p], av[2*p+1]);
        #pragma unroll
        for (int b = 0; b < 8; ++b) {
            float v = fmaf(av[b], mk[b], zr[b]);
            float gv = (type == 2) ? tanh_fast(v) : sigm_fast(v);
            gbuf[j * 9 + b] = gv;
        }
        if (tid < 8) ms[nslot + tid] = 1.f - dn;
        __syncthreads();

        #pragma unroll
        for (int it = 0; it < 2; ++it) {
            int idx = tid + it * 512;
            int b = idx >> 7, u = idx & 127;
            float m = ms[slot + b];
            int gbase = u * 9 + b;
            float iv = gbuf[gbase];
            float fv = gbuf[gbase + 128 * 9];
            float gg = gbuf[gbase + 256 * 9];
            float ov = gbuf[gbase + 384 * 9];
            float cv = fmaf(fv, cbuf[idx] * m, iv * gg);
            float hv = ov * tanh_fast(cv);
            cbuf[idx] = cv;
            hbuf[idx] = hv;
            reinterpret_cast<float*>(hp)[(((b >> 1) << 7) + u) * 2 + (b & 1)] = hv;
        }
        __syncthreads();

        if (tid < 8 * 19) {
            int b = tid / 19, a = tid - b * 19;
            float s0 = 0.f, s1 = 0.f;
            #pragma unroll 4
            for (int k8 = 0; k8 < 16; ++k8) {
                float4 w0 = *reinterpret_cast<const float4*>(&WaCs[a * 132 + k8 * 8]);
                float4 w1 = *reinterpret_cast<const float4*>(&WaCs[a * 132 + k8 * 8 + 4]);
                float4 hv0 = *reinterpret_cast<const float4*>(&hbuf[b * 128 + k8 * 8]);
                float4 hv1 = *reinterpret_cast<const float4*>(&hbuf[b * 128 + k8 * 8 + 4]);
                s0 = fmaf(w0.x, hv0.x, s0); s0 = fmaf(w0.y, hv0.y, s0);
                s0 = fmaf(w0.z, hv0.z, s0); s0 = fmaf(w0.w, hv0.w, s0);
                s1 = fmaf(w1.x, hv1.x, s1); s1 = fmaf(w1.y, hv1.y, s1);
                s1 = fmaf(w1.z, hv1.z, s1); s1 = fmaf(w1.w, hv1.w, s1);
            }
            out[((long)t * BB + gb0 + b) * 19 + a] = s0 + s1 + bac[a];
        }
        __syncthreads();
    }
}

// ---------------------------------------------------------------------------
// Host launcher
// ---------------------------------------------------------------------------
extern "C" void kernel_launch(void* const* d_in, const int* in_sizes, int n_in,
                              void* d_out, int out_size)
{
    const float* x    = (const float*)d_in[0];
    const float* done = (const float*)d_in[1];
    const float* h0   = (const float*)d_in[2];
    const float* c0   = (const float*)d_in[3];
    const float* W1   = (const float*)d_in[4];
    const float* b1   = (const float*)d_in[5];
    const float* W2   = (const float*)d_in[6];
    const float* b2   = (const float*)d_in[7];
    const float* W3   = (const float*)d_in[8];
    const float* b3   = (const float*)d_in[9];
    const float* Wih  = (const float*)d_in[10];
    const float* Whh  = (const float*)d_in[11];
    const float* bih  = (const float*)d_in[12];
    const float* bhh  = (const float*)d_in[13];
    const float* Wa   = (const float*)d_in[14];
    const float* ba   = (const float*)d_in[15];
    const float* Wc   = (const float*)d_in[16];
    const float* bc   = (const float*)d_in[17];
    float* out = (float*)d_out;

    float *h1p, *h2p, *h3p, *Zp;
    cudaGetSymbolAddress((void**)&h1p, g_h1);
    cudaGetSymbolAddress((void**)&h2p, g_h2);
    cudaGetSymbolAddress((void**)&h3p, g_h3);
    cudaGetSymbolAddress((void**)&Zp,  g_Z);

    // big-kernel smem: As KT*128 + Bs KT*(NT+4), fp32
    const int S_BIG_128 = (128 * 128 + 128 * 132) * 4;  // 133120
    const int S_BIG_256 = (128 * 128 + 128 * 260) * 4;  // 198656
    // old-kernel smem
    const int S_128_32  = (128 * 68 + 128 * 36) * 4;    //  53248
    const int S_32_128  = (32  * 68 + 32  * 132) * 4;   //  25600

    cudaFuncSetAttribute(gemm_big<128, 128, true>,
                         cudaFuncAttributeMaxDynamicSharedMemorySize, S_BIG_128);
    cudaFuncSetAttribute(gemm_big<128, 256, false>,
                         cudaFuncAttributeMaxDynamicSharedMemorySize, S_BIG_256);
    cudaFuncSetAttribute(gemm_kernel<128, 32, true>,
                         cudaFuncAttributeMaxDynamicSharedMemorySize, S_128_32);
    cudaFuncSetAttribute(gemm_kernel<32, 128, true>,
                         cudaFuncAttributeMaxDynamicSharedMemorySize, S_32_128);
    cudaFuncSetAttribute(lstm_kernel,
                         cudaFuncAttributeMaxDynamicSharedMemorySize, SMEM_LSTM);

    const int NB128 = MROWS / 128;  // 2048 (big kernel row tiles)
    const int NB64  = MROWS / 64;   // 4096 (old kernel row tiles)

    // Encoder
    gemm_big<128, 128, true><<<dim3(NB128, 1), 512, S_BIG_128>>>(
        x,   W1, b1, nullptr, h1p, 128);
    gemm_kernel<128, 32, true><<<dim3(NB64, 1), 256, S_128_32>>>(
        h1p, W2, b2, nullptr, h2p, 32);
    gemm_kernel<32, 128, true><<<dim3(NB64, 1), 256, S_32_128>>>(
        h2p, W3, b3, nullptr, h3p, 128);
    // Input projection: Z = hid @ Wih^T + bih + bhh  (N=512, 2 col tiles of 256)
    gemm_big<128, 256, false><<<dim3(NB128, 2), 512, S_BIG_256>>>(
        h3p, Wih, bih, bhh, Zp, 512);

    // Recurrence + heads (R10 best variant)
    lstm_kernel<<<128, 512, SMEM_LSTM>>>(
        Zp, done, h0, c0, Whh, Wa, ba, Wc, bc, out);
}

// round 14
// speedup vs baseline: 1.0613x; 1.0222x over previous
#include <cuda_runtime.h>
#include <cuda_fp16.h>
#include <cuda_bf16.h>
#include <cstdint>

// Problem constants
#define TT 256
#define BB 1024
#define OBS 128
#define LS 128
#define HH 128
#define NA 18
#define MROWS (TT*BB)          // 262144

// ---------------------------------------------------------------------------
// Scratch (device globals; no cudaMalloc allowed)
// ---------------------------------------------------------------------------
__device__ float g_h1[(size_t)MROWS * 128];   // encoder layer-1 out
__device__ float g_h2[(size_t)MROWS * 32];    // encoder layer-2 out
__device__ float g_h3[(size_t)MROWS * 128];   // encoder layer-3 out
__device__ float g_Z [(size_t)MROWS * 512];   // precomputed input gates + biases

// ---------------------------------------------------------------------------
// f32x2 packed-FMA helpers (exact fp32 math; 2 MACs per issued inst)
// ---------------------------------------------------------------------------
__device__ __forceinline__ void ffma2(uint64_t& acc, uint64_t a, uint64_t b) {
    asm("fma.rn.f32x2 %0, %1, %2, %0;" : "+l"(acc) : "l"(a), "l"(b));
}
__device__ __forceinline__ uint64_t pack2(float x, float y) {
    uint64_t r;
    asm("mov.b64 %0, {%1, %2};" : "=l"(r) : "f"(x), "f"(y));
    return r;
}
__device__ __forceinline__ void unpack2(uint64_t v, float& lo, float& hi) {
    asm("mov.b64 {%0, %1}, %2;" : "=f"(lo), "=f"(hi) : "l"(v));
}

// ---------------------------------------------------------------------------
// Fast nonlinearities (MUFU; fma pipe stays free)
// ---------------------------------------------------------------------------
__device__ __forceinline__ float sigm_fast(float x) {
    x = fminf(fmaxf(x, -30.f), 30.f);
    return __fdividef(1.f, 1.f + __expf(-x));
}
__device__ __forceinline__ float tanh_fast(float x) {
    x = fminf(fmaxf(x, -15.f), 15.f);
    float e = __expf(-2.f * x);
    return __fdividef(1.f - e, 1.f + e);
}

// ---------------------------------------------------------------------------
// High-intensity GEMM, 512 threads, tile 128 x NT.
// FIX vs R12: B-fragment columns are lane-CONTIGUOUS per float4 group
// (col = g*128 + lane*4), so every LDS.128 is 4 fully-utilized wavefronts
// instead of 8 half-empty ones.  Per warp-k: 10 wavefronts vs 18.
//   C[M][NT-tile] = act( A[M][K] @ W[N][K]^T + b1 (+b2) )
// ---------------------------------------------------------------------------
template<int KT, int NT, bool RELU>
__global__ void __launch_bounds__(512) gemm_big(
    const float* __restrict__ A, const float* __restrict__ W,
    const float* __restrict__ bias1, const float* __restrict__ bias2,
    float* __restrict__ C, int N)
{
    constexpr int BP  = NT + 4;     // padded B leading dim
    constexpr int KQ  = KT / 4;
    constexpr int CPT = NT / 32;    // cols per thread (8 or 4)
    constexpr int NG  = CPT / 4;    // float4 groups per thread (2 or 1)
    constexpr int GS  = NT / NG;    // column-group stride (128)

    extern __shared__ float smg[];
    float* As = smg;                // KT * 128  (A transposed: As[k][row])
    float* Bs = smg + KT * 128;     // KT * BP   (Bs[k][col])

    const int  tid  = threadIdx.x;
    const long row0 = (long)blockIdx.x * 128;
    const int  c0   = blockIdx.y * NT;

    // Stage A tile transposed: 128 rows x KT
    for (int idx = tid; idx < KQ * 128; idx += 512) {
        int kq = idx / 128, r = idx % 128;
        float4 v = *reinterpret_cast<const float4*>(A + (row0 + r) * KT + kq * 4);
        As[(kq*4+0)*128 + r] = v.x;
        As[(kq*4+1)*128 + r] = v.y;
        As[(kq*4+2)*128 + r] = v.z;
        As[(kq*4+3)*128 + r] = v.w;
    }
    // Stage B (=W) tile transposed: NT cols x KT
    for (int idx = tid; idx < KQ * NT; idx += 512) {
        int kq = idx / NT, jj = idx % NT;
        float4 v = *reinterpret_cast<const float4*>(W + (long)(c0 + jj) * KT + kq * 4);
        Bs[(kq*4+0)*BP + jj] = v.x;
        Bs[(kq*4+1)*BP + jj] = v.y;
        Bs[(kq*4+2)*BP + jj] = v.z;
        Bs[(kq*4+3)*BP + jj] = v.w;
    }
    __syncthreads();

    const int lane  = tid & 31;
    const int ty2   = tid >> 5;      // 0..15 -> row group (warp-uniform)
    const int rbase = ty2 * 8;
    const int cg    = lane * 4;      // within-group column base (contiguous!)

    uint64_t acc2[4][CPT];           // [row-pair][g*4+c]
    #pragma unroll
    for (int rp = 0; rp < 4; ++rp)
        #pragma unroll
        for (int c = 0; c < CPT; ++c) acc2[rp][c] = 0ull;

    #pragma unroll 4
    for (int k = 0; k < KT; ++k) {
        // A fragment: 8 row-values, warp-uniform broadcast (2x LDS.128)
        ulonglong2 av0 = *reinterpret_cast<const ulonglong2*>(&As[k * 128 + rbase]);
        ulonglong2 av1 = *reinterpret_cast<const ulonglong2*>(&As[k * 128 + rbase + 4]);
        uint64_t ap[4] = {av0.x, av0.y, av1.x, av1.y};
        // B fragment: NG coalesced float4 loads (512B contiguous per warp)
        float bb[CPT];
        #pragma unroll
        for (int g = 0; g < NG; ++g) {
            float4 bv = *reinterpret_cast<const float4*>(&Bs[k * BP + g * GS + cg]);
            bb[g*4+0] = bv.x; bb[g*4+1] = bv.y; bb[g*4+2] = bv.z; bb[g*4+3] = bv.w;
        }
        #pragma unroll
        for (int c = 0; c < CPT; ++c) {
            uint64_t bd = pack2(bb[c], bb[c]);
            #pragma unroll
            for (int rp = 0; rp < 4; ++rp)
                ffma2(acc2[rp][c], ap[rp], bd);
        }
    }

    // Unpack row pairs
    float acc[8][CPT];
    #pragma unroll
    for (int rp = 0; rp < 4; ++rp)
        #pragma unroll
        for (int c = 0; c < CPT; ++c)
            unpack2(acc2[rp][c], acc[2*rp][c], acc[2*rp+1][c]);

    // Epilogue (per-group contiguous columns)
    float bsum[CPT];
    #pragma unroll
    for (int g = 0; g < NG; ++g)
        #pragma unroll
        for (int c = 0; c < 4; ++c) {
            int col = c0 + g * GS + cg + c;
            bsum[g*4+c] = bias1[col] + (bias2 ? bias2[col] : 0.f);
        }
    #pragma unroll
    for (int i = 0; i < 8; ++i) {
        long row = row0 + rbase + i;
        #pragma unroll
        for (int g = 0; g < NG; ++g) {
            float4 o;
            o.x = acc[i][g*4+0] + bsum[g*4+0];
            o.y = acc[i][g*4+1] + bsum[g*4+1];
            o.z = acc[i][g*4+2] + bsum[g*4+2];
            o.w = acc[i][g*4+3] + bsum[g*4+3];
            if (RELU) {
                o.x = fmaxf(o.x, 0.f); o.y = fmaxf(o.y, 0.f);
                o.z = fmaxf(o.z, 0.f); o.w = fmaxf(o.w, 0.f);
            }
            *reinterpret_cast<float4*>(C + row * N + c0 + g * GS + cg) = o;
        }
    }
}

// ---------------------------------------------------------------------------
// OLD proven GEMM (kept for the small layers W2 / W3)
// ---------------------------------------------------------------------------
template<int KT, int NT, bool RELU>
__global__ void __launch_bounds__(256, 2) gemm_kernel(
    const float* __restrict__ A, const float* __restrict__ W,
    const float* __restrict__ bias1, const float* __restrict__ bias2,
    float* __restrict__ C, int N)
{
    constexpr int AP  = 68;
    constexpr int BP  = NT + 4;
    constexpr int KQ  = KT / 4;
    constexpr int CPT = NT / 32;

    extern __shared__ float smg[];
    float* As = smg;
    float* Bs = smg + KT * AP;

    const int  tid  = threadIdx.x;
    const long row0 = (long)blockIdx.x * 64;
    const int  c0   = blockIdx.y * NT;

    for (int idx = tid; idx < KQ * 64; idx += 256) {
        int kq = idx / 64, r = idx % 64;
        float4 v = *reinterpret_cast<const float4*>(A + (row0 + r) * KT + kq * 4);
        As[(kq*4+0)*AP + r] = v.x;
        As[(kq*4+1)*AP + r] = v.y;
        As[(kq*4+2)*AP + r] = v.z;
        As[(kq*4+3)*AP + r] = v.w;
    }
    for (int idx = tid; idx < KQ * NT; idx += 256) {
        int kq = idx / NT, jj = idx % NT;
        float4 v = *reinterpret_cast<const float4*>(W + (long)(c0 + jj) * KT + kq * 4);
        Bs[(kq*4+0)*BP + jj] = v.x;
        Bs[(kq*4+1)*BP + jj] = v.y;
        Bs[(kq*4+2)*BP + jj] = v.z;
        Bs[(kq*4+3)*BP + jj] = v.w;
    }
    __syncthreads();

    const int tx = tid & 31, ty = tid >> 5;
    uint64_t acc2[4][CPT];
    #pragma unroll
    for (int i2 = 0; i2 < 4; ++i2)
        #pragma unroll
        for (int c = 0; c < CPT; ++c) acc2[i2][c] = 0ull;

    #pragma unroll 8
    for (int k = 0; k < KT; ++k) {
        ulonglong2 av0 = *reinterpret_cast<const ulonglong2*>(&As[k * AP + ty * 8]);
        ulonglong2 av1 = *reinterpret_cast<const ulonglong2*>(&As[k * AP + ty * 8 + 4]);
        uint64_t ap[4] = {av0.x, av0.y, av1.x, av1.y};
        float bb[CPT];
        if constexpr (CPT == 4) {
            float4 bv = *reinterpret_cast<const float4*>(&Bs[k * BP + tx * 4]);
            bb[0] = bv.x; bb[1] = bv.y; bb[2] = bv.z; bb[3] = bv.w;
        } else {
            bb[0] = Bs[k * BP + tx];
        }
        #pragma unroll
        for (int c = 0; c < CPT; ++c) {
            uint64_t bd = pack2(bb[c], bb[c]);
            #pragma unroll
            for (int i2 = 0; i2 < 4; ++i2)
                ffma2(acc2[i2][c], ap[i2], bd);
        }
    }

    float acc[8][CPT];
    #pragma unroll
    for (int i2 = 0; i2 < 4; ++i2)
        #pragma unroll
        for (int c = 0; c < CPT; ++c)
            unpack2(acc2[i2][c], acc[2*i2][c], acc[2*i2+1][c]);

    if constexpr (CPT == 4) {
        float bsum[4];
        #pragma unroll
        for (int c = 0; c < 4; ++c) {
            int col = c0 + tx * 4 + c;
            bsum[c] = bias1[col] + (bias2 ? bias2[col] : 0.f);
        }
        #pragma unroll
        for (int i = 0; i < 8; ++i) {
            long row = row0 + ty * 8 + i;
            float4 o;
            o.x = acc[i][0] + bsum[0];
            o.y = acc[i][1] + bsum[1];
            o.z = acc[i][2] + bsum[2];
            o.w = acc[i][3] + bsum[3];
            if (RELU) {
                o.x = fmaxf(o.x, 0.f); o.y = fmaxf(o.y, 0.f);
                o.z = fmaxf(o.z, 0.f); o.w = fmaxf(o.w, 0.f);
            }
            *reinterpret_cast<float4*>(C + row * N + c0 + tx * 4) = o;
        }
    } else {
        int col = c0 + tx;
        float bsum = bias1[col] + (bias2 ? bias2[col] : 0.f);
        #pragma unroll
        for (int i = 0; i < 8; ++i) {
            long row = row0 + ty * 8 + i;
            float v = acc[i][0] + bsum;
            if (RELU) v = fmaxf(v, 0.f);
            C[row * N + col] = v;
        }
    }
}

// ---------------------------------------------------------------------------
// Persistent LSTM recurrence + heads (R10 best variant, byte-identical).
// 128 CTAs x 512 threads; 8 lanes/CTA; Whh fp16 smem; f32x2 matvec.
// ---------------------------------------------------------------------------
#define OFF_WSH   0                         // 512*128 half   = 131072
#define OFF_HBUF  131072                    // 8*128 f32      =   4096
#define OFF_CBUF  135168                    //                =   4096
#define OFF_HP    139264                    // 4*128 float2   =   4096
#define OFF_GBUF  143360                    // 512*9 f32      =  18432
#define OFF_WAC   161792                    // 19*132 f32     =  10048 (pad)
#define OFF_BAC   171840                    // 19 f32         =     80 (pad)
#define OFF_MS    171920                    // 2*8 f32        =     64
#define SMEM_LSTM 171984

__global__ void __launch_bounds__(512, 1) lstm_kernel(
    const float* __restrict__ Z,    const float* __restrict__ done,
    const float* __restrict__ h0,   const float* __restrict__ c0,
    const float* __restrict__ Whh,
    const float* __restrict__ Wa,   const float* __restrict__ ba,
    const float* __restrict__ Wc,   const float* __restrict__ bc,
    float* __restrict__ out)
{
    extern __shared__ char smraw[];
    __half*  wsh  = reinterpret_cast<__half*>(smraw + OFF_WSH);
    float*   hbuf = reinterpret_cast<float*>(smraw + OFF_HBUF);
    float*   cbuf = reinterpret_cast<float*>(smraw + OFF_CBUF);
    float2*  hp   = reinterpret_cast<float2*>(smraw + OFF_HP);
    float*   gbuf = reinterpret_cast<float*>(smraw + OFF_GBUF);
    float*   WaCs = reinterpret_cast<float*>(smraw + OFF_WAC);
    float*   bac  = reinterpret_cast<float*>(smraw + OFF_BAC);
    float*   ms   = reinterpret_cast<float*>(smraw + OFF_MS);

    const int tid = threadIdx.x;
    const int gb0 = blockIdx.x * 8;        // 128 CTAs x 8 lanes = 1024

    for (int idx = tid; idx < 512 * 128; idx += 512) {
        int jj = idx >> 7, k = idx & 127;
        wsh[((k >> 2) << 11) + (jj << 2) + (k & 3)] = __float2half(Whh[idx]);
    }
    for (int idx = tid; idx < 8 * 128; idx += 512) {
        int b = idx >> 7, u = idx & 127;
        hbuf[idx] = h0[(gb0 + b) * HH + u];
        cbuf[idx] = c0[(gb0 + b) * HH + u];
    }
    for (int idx = tid; idx < 4 * 128; idx += 512) {
        int p = idx >> 7, k = idx & 127;
        hp[p * 128 + k] = make_float2(h0[(gb0 + 2*p) * HH + k],
                                      h0[(gb0 + 2*p + 1) * HH + k]);
    }
    for (int idx = tid; idx < 19 * 128; idx += 512) {
        int a = idx >> 7, k = idx & 127;
        WaCs[a * 132 + k] = (a < 18) ? Wa[a * 128 + k] : Wc[k];
    }
    if (tid < 19) bac[tid] = (tid < 18) ? ba[tid] : bc[0];
    if (tid < 8)  ms[tid]  = 1.f - done[gb0 + tid];
    __syncthreads();

    const int j    = tid;
    const int type = j >> 7;

    for (int t = 0; t < TT; ++t) {
        const int slot  = (t & 1) * 8;
        const int nslot = ((t + 1) & 1) * 8;

        float zr[8];
        const long zbase = ((long)t * BB + gb0) * 512 + j;
        #pragma unroll
        for (int b = 0; b < 8; ++b)
            zr[b] = Z[zbase + (long)b * 512];
        float dn = 0.f;
        if (tid < 8)
            dn = (t < TT - 1) ? done[(t + 1) * BB + gb0 + tid] : 0.f;
        float mk[8];
        #pragma unroll
        for (int b = 0; b < 8; ++b) mk[b] = ms[slot + b];

        uint64_t acc2[4] = {0ull, 0ull, 0ull, 0ull};
        #pragma unroll 4
        for (int k4 = 0; k4 < 32; ++k4) {
            uint2 wr = *reinterpret_cast<const uint2*>(wsh + (k4 << 11) + (j << 2));
            float2 w01 = __half22float2(*reinterpret_cast<const __half2*>(&wr.x));
            float2 w23 = __half22float2(*reinterpret_cast<const __half2*>(&wr.y));
            uint64_t wd0 = pack2(w01.x, w01.x);
            uint64_t wd1 = pack2(w01.y, w01.y);
            uint64_t wd2 = pack2(w23.x, w23.x);
            uint64_t wd3 = pack2(w23.y, w23.y);
            ulonglong2 ha[4], hb[4];
            #pragma unroll
            for (int p = 0; p < 4; ++p) {
                ha[p] = *reinterpret_cast<const ulonglong2*>(&hp[(p << 7) + (k4 << 2)]);
                hb[p] = *reinterpret_cast<const ulonglong2*>(&hp[(p << 7) + (k4 << 2) + 2]);
            }
            #pragma unroll
            for (int p = 0; p < 4; ++p) ffma2(acc2[p], wd0, ha[p].x);
            #pragma unroll
            for (int p = 0; p < 4; ++p) ffma2(acc2[p], wd1, ha[p].y);
            #pragma unroll
            for (int p = 0; p < 4; ++p) ffma2(acc2[p], wd2, hb[p].x);
            #pragma unroll
            for (int p = 0; p < 4; ++p) ffma2(acc2[p], wd3, hb[p].y);
        }
        float av[8];
        #pragma unroll
        for (int p = 0; p < 4; ++p) unpack2(acc2[p], av[2*p], av[2*p+1]);
        #pragma unroll
        for (int b = 0; b < 8; ++b) {
            float v = fmaf(av[b], mk[b], zr[b]);
            float gv = (type == 2) ? tanh_fast(v) : sigm_fast(v);
            gbuf[j * 9 + b] = gv;
        }
        if (tid < 8) ms[nslot + tid] = 1.f - dn;
        __syncthreads();

        #pragma unroll
        for (int it = 0; it < 2; ++it) {
            int idx = tid + it * 512;
            int b = idx >> 7, u = idx & 127;
            float m = ms[slot + b];
            int gbase = u * 9 + b;
            float iv = gbuf[gbase];
            float fv = gbuf[gbase + 128 * 9];
            float gg = gbuf[gbase + 256 * 9];
            float ov = gbuf[gbase + 384 * 9];
            float cv = fmaf(fv, cbuf[idx] * m, iv * gg);
            float hv = ov * tanh_fast(cv);
            cbuf[idx] = cv;
            hbuf[idx] = hv;
            reinterpret_cast<float*>(hp)[(((b >> 1) << 7) + u) * 2 + (b & 1)] = hv;
        }
        __syncthreads();

        if (tid < 8 * 19) {
            int b = tid / 19, a = tid - b * 19;
            float s0 = 0.f, s1 = 0.f;
            #pragma unroll 4
            for (int k8 = 0; k8 < 16; ++k8) {
                float4 w0 = *reinterpret_cast<const float4*>(&WaCs[a * 132 + k8 * 8]);
                float4 w1 = *reinterpret_cast<const float4*>(&WaCs[a * 132 + k8 * 8 + 4]);
                float4 hv0 = *reinterpret_cast<const float4*>(&hbuf[b * 128 + k8 * 8]);
                float4 hv1 = *reinterpret_cast<const float4*>(&hbuf[b * 128 + k8 * 8 + 4]);
                s0 = fmaf(w0.x, hv0.x, s0); s0 = fmaf(w0.y, hv0.y, s0);
                s0 = fmaf(w0.z, hv0.z, s0); s0 = fmaf(w0.w, hv0.w, s0);
                s1 = fmaf(w1.x, hv1.x, s1); s1 = fmaf(w1.y, hv1.y, s1);
                s1 = fmaf(w1.z, hv1.z, s1); s1 = fmaf(w1.w, hv1.w, s1);
            }
            out[((long)t * BB + gb0 + b) * 19 + a] = s0 + s1 + bac[a];
        }
        __syncthreads();
    }
}

// ---------------------------------------------------------------------------
// Host launcher
// ---------------------------------------------------------------------------
extern "C" void kernel_launch(void* const* d_in, const int* in_sizes, int n_in,
                              void* d_out, int out_size)
{
    const float* x    = (const float*)d_in[0];
    const float* done = (const float*)d_in[1];
    const float* h0   = (const float*)d_in[2];
    const float* c0   = (const float*)d_in[3];
    const float* W1   = (const float*)d_in[4];
    const float* b1   = (const float*)d_in[5];
    const float* W2   = (const float*)d_in[6];
    const float* b2   = (const float*)d_in[7];
    const float* W3   = (const float*)d_in[8];
    const float* b3   = (const float*)d_in[9];
    const float* Wih  = (const float*)d_in[10];
    const float* Whh  = (const float*)d_in[11];
    const float* bih  = (const float*)d_in[12];
    const float* bhh  = (const float*)d_in[13];
    const float* Wa   = (const float*)d_in[14];
    const float* ba   = (const float*)d_in[15];
    const float* Wc   = (const float*)d_in[16];
    const float* bc   = (const float*)d_in[17];
    float* out = (float*)d_out;

    float *h1p, *h2p, *h3p, *Zp;
    cudaGetSymbolAddress((void**)&h1p, g_h1);
    cudaGetSymbolAddress((void**)&h2p, g_h2);
    cudaGetSymbolAddress((void**)&h3p, g_h3);
    cudaGetSymbolAddress((void**)&Zp,  g_Z);

    // big-kernel smem: As KT*128 + Bs KT*(NT+4), fp32
    const int S_BIG_128 = (128 * 128 + 128 * 132) * 4;  // 133120
    const int S_BIG_256 = (128 * 128 + 128 * 260) * 4;  // 198656
    // old-kernel smem
    const int S_128_32  = (128 * 68 + 128 * 36) * 4;    //  53248
    const int S_32_128  = (32  * 68 + 32  * 132) * 4;   //  25600

    cudaFuncSetAttribute(gemm_big<128, 128, true>,
                         cudaFuncAttributeMaxDynamicSharedMemorySize, S_BIG_128);
    cudaFuncSetAttribute(gemm_big<128, 256, false>,
                         cudaFuncAttributeMaxDynamicSharedMemorySize, S_BIG_256);
    cudaFuncSetAttribute(gemm_kernel<128, 32, true>,
                         cudaFuncAttributeMaxDynamicSharedMemorySize, S_128_32);
    cudaFuncSetAttribute(gemm_kernel<32, 128, true>,
                         cudaFuncAttributeMaxDynamicSharedMemorySize, S_32_128);
    cudaFuncSetAttribute(lstm_kernel,
                         cudaFuncAttributeMaxDynamicSharedMemorySize, SMEM_LSTM);

    const int NB128 = MROWS / 128;  // 2048 (big kernel row tiles)
    const int NB64  = MROWS / 64;   // 4096 (old kernel row tiles)

    // Encoder
    gemm_big<128, 128, true><<<dim3(NB128, 1), 512, S_BIG_128>>>(
        x,   W1, b1, nullptr, h1p, 128);
    gemm_kernel<128, 32, true><<<dim3(NB64, 1), 256, S_128_32>>>(
        h1p, W2, b2, nullptr, h2p, 32);
    gemm_kernel<32, 128, true><<<dim3(NB64, 1), 256, S_32_128>>>(
        h2p, W3, b3, nullptr, h3p, 128);
    // Input projection: Z = hid @ Wih^T + bih + bhh  (N=512, 2 col tiles of 256)
    gemm_big<128, 256, false><<<dim3(NB128, 2), 512, S_BIG_256>>>(
        h3p, Wih, bih, bhh, Zp, 512);

    // Recurrence + heads (R10 best variant)
    lstm_kernel<<<128, 512, SMEM_LSTM>>>(
        Zp, done, h0, c0, Whh, Wa, ba, Wc, bc, out);
}